// round 1
// baseline (speedup 1.0000x reference)
#include <cuda_runtime.h>
#include <cuda_bf16.h>
#include <math_constants.h>

// Problem constants
#define NB   2
#define NCI  32
#define NCO  32
#define NN   64
#define NM   8     // modes per corner per axis
#define MM   16    // total x/y modes kept
#define BCN  (NB*NCI)   // 64
#define SCALE 3.814697265625e-06f  // 1/64^3

// ---------------- scratch (device globals; no allocation allowed) -------------
__device__ float T1[BCN*64*64*8*2];     // [bc][x][y][kz][2]     16.8 MB
__device__ float T2[BCN*64*16*8*2];     // [bc][x][ky][kz][2]     4.2 MB
__device__ float T3[BCN*16*16*8];       // [bc][mx][my][kz]       0.5 MB
__device__ float T4[NB*NCO*16*16*8*2];  // [bco][mx][my][kz][2]   1.0 MB
__device__ float T5[NB*NCO*16*64*16*2]; // [bco][mx][z][my][2]    8.4 MB
__device__ float T6[NB*NCO*64*16*64*2]; // [bco][y][mx][z][2]    33.6 MB

// twiddle tables
__device__ float d_FZ[64*8*2];    // [z][kz][2]  e^{-i 2pi kz z/64}
__device__ float d_FY[64*16*2];   // [y][m][2]   e^{-i 2pi km y/64}
__device__ float d_FX[64*16*2];   // [x][m][2]
__device__ float d_IZ[8*64*2];    // [kz][z][2]  e^{+i}*SCALE
__device__ float d_IY[16*64*2];   // [m][y][2]   e^{+i}
__device__ float d_IX[16*64*2];   // [m][x][2]

// ---------------- twiddle init ----------------
__global__ void k_init() {
    int t = threadIdx.x;
    for (int i = t; i < 64*8; i += 256) {
        int z = i >> 3, kz = i & 7;
        float s, c; sincospif((float)(z*kz) / 32.0f, &s, &c);
        d_FZ[i*2+0] = c; d_FZ[i*2+1] = -s;
    }
    for (int i = t; i < 64*16; i += 256) {
        int n = i >> 4, m = i & 15;
        int k = (m < 8) ? m : (m + 48);
        float s, c; sincospif((float)(n*k) / 32.0f, &s, &c);
        d_FY[i*2] = c; d_FY[i*2+1] = -s;
        d_FX[i*2] = c; d_FX[i*2+1] = -s;
    }
    for (int i = t; i < 8*64; i += 256) {
        int kz = i >> 6, z = i & 63;
        float s, c; sincospif((float)(z*kz) / 32.0f, &s, &c);
        d_IZ[i*2] = c * SCALE; d_IZ[i*2+1] = s * SCALE;
    }
    for (int i = t; i < 16*64; i += 256) {
        int m = i >> 6, n = i & 63;
        int k = (m < 8) ? m : (m + 48);
        float s, c; sincospif((float)(n*k) / 32.0f, &s, &c);
        d_IY[i*2] = c; d_IY[i*2+1] = s;
        d_IX[i*2] = c; d_IX[i*2+1] = s;
    }
}

// ---------------- F1: z-reduce  x[bc][x][y][z] -> T1[bc][x][y][kz][2] --------
__global__ void k_f1(const float* __restrict__ gx) {
    __shared__ float sx[2*64*65];      // [xi][y][z] padded rows
    __shared__ float sFZ[64*16];       // [z][kz*2+p]
    int blk = blockIdx.x;              // 2048 = 64 bc * 32 x-pairs
    int bc = blk >> 5;
    int x0 = (blk & 31) << 1;
    int t = threadIdx.x;
    for (int i = t; i < 64*16; i += 256) sFZ[i] = d_FZ[i];
    const float* src = gx + ((size_t)bc*64 + x0) * 4096;
    for (int i = t; i < 8192; i += 256) {
        int xi = i >> 12, r = i & 4095;
        int y = r >> 6, z = r & 63;
        sx[xi*4160 + y*65 + z] = src[i];
    }
    __syncthreads();
    int xi = t >> 7;
    int u  = t & 127;
    int kz = u & 7;
    int ys = (u >> 3) << 2;
    float ar0=0,ai0=0,ar1=0,ai1=0,ar2=0,ai2=0,ar3=0,ai3=0;
    const float* px = &sx[xi*4160 + ys*65];
    #pragma unroll 4
    for (int z = 0; z < 64; z++) {
        float c = sFZ[z*16 + kz*2];
        float s = sFZ[z*16 + kz*2 + 1];
        float v0 = px[z], v1 = px[65+z], v2 = px[130+z], v3 = px[195+z];
        ar0 += v0*c; ai0 += v0*s;
        ar1 += v1*c; ai1 += v1*s;
        ar2 += v2*c; ai2 += v2*s;
        ar3 += v3*c; ai3 += v3*s;
    }
    float* dst = T1 + (((size_t)bc*64 + x0 + xi)*64 + ys)*16 + kz*2;
    dst[0]  = ar0; dst[1]  = ai0;
    dst[16] = ar1; dst[17] = ai1;
    dst[32] = ar2; dst[33] = ai2;
    dst[48] = ar3; dst[49] = ai3;
}

// ---------------- F2: y-reduce  T1 -> T2[bc][x][ky][kz][2] -------------------
__global__ void k_f2() {
    __shared__ __align__(16) float sT1[8192];   // [xi][y*16 + kz*2+p]
    __shared__ __align__(16) float sFY[2048];   // [y*32 + ky*2 + p]
    int blk = blockIdx.x;      // 512 = 64 bc * 8 x-octets
    int bc = blk >> 3;
    int x0 = (blk & 7) << 3;
    int t = threadIdx.x;
    const float* src = T1 + ((size_t)bc*64 + x0) * 1024;
    for (int i = t; i < 8192; i += 256) sT1[i] = src[i];
    for (int i = t; i < 2048; i += 256) sFY[i] = d_FY[i];
    __syncthreads();
    int xi  = t >> 5;
    int v   = t & 31;
    int kyt = (v & 7) << 1;
    int kzt = (v >> 3) << 1;
    float or00=0,oi00=0,or01=0,oi01=0,or10=0,oi10=0,or11=0,oi11=0;
    const float* pa = &sT1[xi*1024 + kzt*2];
    const float* pe = &sFY[kyt*2];
    #pragma unroll 4
    for (int y = 0; y < 64; y++) {
        float4 a = *(const float4*)(pa + y*16);   // (aR0,aI0,aR1,aI1) kz pair
        float4 e = *(const float4*)(pe + y*32);   // (eR0,eI0,eR1,eI1) ky pair
        or00 += a.x*e.x - a.y*e.y;  oi00 += a.x*e.y + a.y*e.x;
        or01 += a.z*e.x - a.w*e.y;  oi01 += a.z*e.y + a.w*e.x;
        or10 += a.x*e.z - a.y*e.w;  oi10 += a.x*e.w + a.y*e.z;
        or11 += a.z*e.z - a.w*e.w;  oi11 += a.z*e.w + a.w*e.z;
    }
    float* d0 = T2 + ((size_t)bc*64 + x0 + xi)*256 + kyt*16 + kzt*2;
    d0[0]=or00; d0[1]=oi00; d0[2]=or01; d0[3]=oi01;
    d0[16]=or10; d0[17]=oi10; d0[18]=or11; d0[19]=oi11;
}

// ---------------- F3: x-reduce + Re  T2 -> T3[bc][mx][my][kz] ----------------
__global__ void k_f3() {
    __shared__ float sT2[4096];   // chunk [16x][ky*16+kz*2+p]
    __shared__ float sFX[2048];   // [x*32 + kx*2 + p]
    int blk = blockIdx.x;         // 128 = 64 bc * 2 kx-halves
    int bc = blk >> 1;
    int h  = blk & 1;
    int t = threadIdx.x;
    for (int i = t; i < 2048; i += 256) sFX[i] = d_FX[i];
    int q  = t >> 7;
    int w  = t & 127;
    int ky = w >> 3, kz = w & 7;
    int kx0 = h*8 + q*4;
    float a0=0,a1=0,a2=0,a3=0;
    for (int xc = 0; xc < 4; xc++) {
        __syncthreads();
        const float* src = T2 + ((size_t)bc*64 + xc*16) * 256;
        for (int i = t; i < 4096; i += 256) sT2[i] = src[i];
        __syncthreads();
        #pragma unroll 4
        for (int xi = 0; xi < 16; xi++) {
            float aR = sT2[xi*256 + ky*16 + kz*2];
            float aI = sT2[xi*256 + ky*16 + kz*2 + 1];
            const float* pe = &sFX[(xc*16+xi)*32 + kx0*2];
            a0 += aR*pe[0] - aI*pe[1];
            a1 += aR*pe[2] - aI*pe[3];
            a2 += aR*pe[4] - aI*pe[5];
            a3 += aR*pe[6] - aI*pe[7];
        }
    }
    float* dst = T3 + (size_t)bc*2048 + kx0*128 + ky*8 + kz;
    dst[0]=a0; dst[128]=a1; dst[256]=a2; dst[384]=a3;
}

// ---------------- C: channel mix  T3 x W -> T4[bco][mid][2] ------------------
__global__ void k_c(const float* __restrict__ w1r, const float* __restrict__ w1i,
                    const float* __restrict__ w2r, const float* __restrict__ w2i,
                    const float* __restrict__ w3r, const float* __restrict__ w3i,
                    const float* __restrict__ w4r, const float* __restrict__ w4i) {
    int blk = blockIdx.x;     // 64 = 2 b * 32 co
    int co = blk & 31;
    int b  = blk >> 5;
    int t = threadIdx.x;
    float accR[8], accI[8];
    const float* wr[8]; const float* wi[8];
    int woff[8];
    #pragma unroll
    for (int j = 0; j < 8; j++) {
        accR[j]=0.f; accI[j]=0.f;
        int mid = t + 256*j;
        int mx = mid >> 7, my = (mid >> 3) & 15, kz = mid & 7;
        int sel = (my >> 3)*2 + (mx >> 3);
        wr[j] = (sel==0) ? w1r : (sel==1) ? w2r : (sel==2) ? w3r : w4r;
        wi[j] = (sel==0) ? w1i : (sel==1) ? w2i : (sel==2) ? w3i : w4i;
        woff[j] = (co*8 + (mx&7))*64 + (my&7)*8 + kz;
    }
    for (int ci = 0; ci < 32; ci++) {
        const float* xdp = T3 + ((size_t)(b*32 + ci))*2048 + t;
        int wbase = ci * NCO * 512;
        #pragma unroll
        for (int j = 0; j < 8; j++) {
            float xd = xdp[256*j];
            accR[j] += xd * wr[j][wbase + woff[j]];
            accI[j] += xd * wi[j][wbase + woff[j]];
        }
    }
    float* dst = T4 + ((size_t)(b*32 + co))*4096 + t*2;
    #pragma unroll
    for (int j = 0; j < 8; j++) {
        dst[512*j]     = accR[j];
        dst[512*j + 1] = accI[j];
    }
}

// ---------------- I1: kz expand  T4 -> T5[bco][mx][z][my][2] -----------------
__global__ void k_i1() {
    __shared__ float sT4[256];     // [my][kz][2]
    __shared__ float sIZ[1024];    // [kz][z][2]
    int blk = blockIdx.x;          // 1024 = 64 bco * 16 mx
    int bco = blk >> 4;
    int mx  = blk & 15;
    int t = threadIdx.x;
    const float* src = T4 + ((size_t)bco*2048 + mx*128) * 2;
    sT4[t] = src[t];
    for (int i = t; i < 1024; i += 256) sIZ[i] = d_IZ[i];
    __syncthreads();
    int z   = t >> 2;
    int my0 = (t & 3) << 2;
    float accR[4] = {0,0,0,0}, accI[4] = {0,0,0,0};
    #pragma unroll
    for (int kz = 0; kz < 8; kz++) {
        float ezR = sIZ[kz*128 + z*2];
        float ezI = sIZ[kz*128 + z*2 + 1];
        #pragma unroll
        for (int j = 0; j < 4; j++) {
            float aR = sT4[(my0+j)*16 + kz*2];
            float aI = sT4[(my0+j)*16 + kz*2 + 1];
            accR[j] += aR*ezR - aI*ezI;
            accI[j] += aR*ezI + aI*ezR;
        }
    }
    float* dst = T5 + ((((size_t)bco*16 + mx)*64 + z)*16 + my0)*2;
    #pragma unroll
    for (int j = 0; j < 4; j++) { dst[j*2]=accR[j]; dst[j*2+1]=accI[j]; }
}

// ---------------- I2: y expand  T5 -> T6[bco][y][mx][z][2] -------------------
__global__ void k_i2() {
    __shared__ float sr[64*17], si[64*17];   // [z][my] padded, split r/i
    __shared__ float sIY[2048];              // [my*128 + y*2 + p]
    int blk = blockIdx.x;      // 1024 = 64 bco * 16 mx
    int bco = blk >> 4;
    int mx  = blk & 15;
    int t = threadIdx.x;
    const float* src = T5 + ((size_t)bco*16 + mx) * 2048;
    for (int i = t; i < 2048; i += 256) {
        float v = src[i];
        int z = i >> 5, r = i & 31, my = r >> 1;
        if (r & 1) si[z*17+my] = v; else sr[z*17+my] = v;
    }
    for (int i = t; i < 2048; i += 256) sIY[i] = d_IY[i];
    __syncthreads();
    int z  = t & 63;
    int yg = t >> 6;
    float accR[16], accI[16];
    #pragma unroll
    for (int j = 0; j < 16; j++) { accR[j]=0.f; accI[j]=0.f; }
    #pragma unroll 2
    for (int my = 0; my < 16; my++) {
        float aR = sr[z*17+my], aI = si[z*17+my];
        const float* pe = &sIY[my*128 + yg*32];
        #pragma unroll
        for (int yi = 0; yi < 16; yi++) {
            float eR = pe[yi*2], eI = pe[yi*2+1];
            accR[yi] += aR*eR - aI*eI;
            accI[yi] += aR*eI + aI*eR;
        }
    }
    #pragma unroll
    for (int yi = 0; yi < 16; yi++) {
        int y = yg*16 + yi;
        float* dst = T6 + (size_t)(bco*64 + y)*2048 + mx*128 + z*2;
        dst[0] = accR[yi]; dst[1] = accI[yi];
    }
}

// ---------------- I3: x expand + Re  T6 -> out[bco][x][y][z] -----------------
__global__ void k_i3(float* __restrict__ out) {
    __shared__ __align__(16) float sr[1024], si[1024];    // [mx*64+z]
    __shared__ float ser[1024], sei[1024];                // IX [mx*64+x]
    int blk = blockIdx.x;   // 4096 = 64 bco * 64 y
    int bco = blk >> 6;
    int y   = blk & 63;
    int t = threadIdx.x;
    const float* src = T6 + ((size_t)bco*64 + y) * 2048;
    for (int i = t; i < 2048; i += 256) {
        float v = src[i];
        int mx = i >> 7, r = i & 127, z = r >> 1;
        if (r & 1) si[mx*64+z] = v; else sr[mx*64+z] = v;
    }
    for (int i = t; i < 2048; i += 256) {
        float v = d_IX[i];
        int mx = i >> 7, r = i & 127, x = r >> 1;
        if (r & 1) sei[mx*64+x] = v; else ser[mx*64+x] = v;
    }
    __syncthreads();
    int zq = t & 15;
    int xg = t >> 4;
    float acc[4][4];
    #pragma unroll
    for (int i = 0; i < 4; i++)
        #pragma unroll
        for (int j = 0; j < 4; j++) acc[i][j] = 0.f;
    #pragma unroll 2
    for (int mx = 0; mx < 16; mx++) {
        float4 aR = *(const float4*)&sr[mx*64 + zq*4];
        float4 aI = *(const float4*)&si[mx*64 + zq*4];
        #pragma unroll
        for (int i = 0; i < 4; i++) {
            int x = xg*4 + i;
            float eR = ser[mx*64 + x];
            float eI = sei[mx*64 + x];
            acc[i][0] += aR.x*eR - aI.x*eI;
            acc[i][1] += aR.y*eR - aI.y*eI;
            acc[i][2] += aR.z*eR - aI.z*eI;
            acc[i][3] += aR.w*eR - aI.w*eI;
        }
    }
    #pragma unroll
    for (int i = 0; i < 4; i++) {
        int x = xg*4 + i;
        float4 v = make_float4(acc[i][0], acc[i][1], acc[i][2], acc[i][3]);
        *(float4*)&out[((size_t)bco*64 + x)*4096 + y*64 + zq*4] = v;
    }
}

// ---------------- launch -----------------------------------------------------
extern "C" void kernel_launch(void* const* d_in, const int* in_sizes, int n_in,
                              void* d_out, int out_size) {
    const float* x   = (const float*)d_in[0];
    const float* w1r = (const float*)d_in[1];
    const float* w1i = (const float*)d_in[2];
    const float* w2r = (const float*)d_in[3];
    const float* w2i = (const float*)d_in[4];
    const float* w3r = (const float*)d_in[5];
    const float* w3i = (const float*)d_in[6];
    const float* w4r = (const float*)d_in[7];
    const float* w4i = (const float*)d_in[8];
    float* out = (float*)d_out;

    k_init<<<1, 256>>>();
    k_f1<<<2048, 256>>>(x);
    k_f2<<<512, 256>>>();
    k_f3<<<128, 256>>>();
    k_c<<<64, 256>>>(w1r, w1i, w2r, w2i, w3r, w3i, w4r, w4i);
    k_i1<<<1024, 256>>>();
    k_i2<<<1024, 256>>>();
    k_i3<<<4096, 256>>>(out);
}

// round 2
// speedup vs baseline: 1.6998x; 1.6998x over previous
#include <cuda_runtime.h>
#include <cuda_bf16.h>
#include <math_constants.h>

#define NB   2
#define NCI  32
#define NCO  32
#define SCALE 3.814697265625e-06f  // 1/64^3

// ---------------- scratch (device globals) -----------------------------------
__device__ float T2[64*64*16*8*2];      // [bc][x][ky][kz]c      4.2 MB
__device__ float T3[64*16*16*8];        // [bc][kx][ky][kz]      0.5 MB
__device__ float T4[64*16*16*8*2];      // [bco][mx][my][kz]c    1.0 MB
__device__ float T5[64*64*16*8*2];      // [bco][x][my][kz]c     4.2 MB

// twiddle tables
__device__ float d_FZ[64*8*2];    // [z][kz]c   e^{-i 2pi kz z/64}
__device__ float d_FY[64*16*2];   // [y][ky]c
__device__ float d_FX[64*16*2];   // [x][kx]c
__device__ float d_IZ[8*64*2];    // [kz][z]c   e^{+i}*SCALE
__device__ float d_IY[16*64*2];   // [my][y]c   e^{+i}
__device__ float d_IX[16*64*2];   // [mx][x]c

__global__ void k_init() {
    int t = threadIdx.x;
    for (int i = t; i < 64*8; i += 256) {
        int z = i >> 3, kz = i & 7;
        float s, c; sincospif((float)(z*kz) / 32.0f, &s, &c);
        d_FZ[i*2+0] = c; d_FZ[i*2+1] = -s;
    }
    for (int i = t; i < 64*16; i += 256) {
        int n = i >> 4, m = i & 15;
        int k = (m < 8) ? m : (m + 48);
        float s, c; sincospif((float)(n*k) / 32.0f, &s, &c);
        d_FY[i*2] = c; d_FY[i*2+1] = -s;
        d_FX[i*2] = c; d_FX[i*2+1] = -s;
    }
    for (int i = t; i < 8*64; i += 256) {
        int kz = i >> 6, z = i & 63;
        float s, c; sincospif((float)(z*kz) / 32.0f, &s, &c);
        d_IZ[i*2] = c * SCALE; d_IZ[i*2+1] = s * SCALE;
    }
    for (int i = t; i < 16*64; i += 256) {
        int m = i >> 6, n = i & 63;
        int k = (m < 8) ? m : (m + 48);
        float s, c; sincospif((float)(n*k) / 32.0f, &s, &c);
        d_IY[i*2] = c; d_IY[i*2+1] = s;
        d_IX[i*2] = c; d_IX[i*2+1] = s;
    }
}

// ---------- F12: fused z-reduce + y-reduce  x -> T2[bc][x][ky][kz]c ----------
// grid 1024 = 64 bc * 16 x-quads, 256 threads
__global__ void k_f12(const float* __restrict__ gx) {
    __shared__ float sx[64*65];        // [z][y] transposed, padded
    __shared__ float sA[4*8*130];      // [xi][kz][y]c  row stride 130
    __shared__ float sFZ[64*16];       // [z][kz]c
    __shared__ float sFY[64*32];       // [y][ky]c
    int blk = blockIdx.x;
    int bc = blk >> 4;
    int x0 = (blk & 15) << 2;
    int t = threadIdx.x;
    for (int i = t; i < 1024; i += 256) sFZ[i] = d_FZ[i];
    for (int i = t; i < 2048; i += 256) sFY[i] = d_FY[i];

    int kzp = t & 3;       // kz pair = {2kzp, 2kzp+1}
    int y   = t >> 2;      // 0..63
    for (int xi = 0; xi < 4; xi++) {
        __syncthreads();
        const float* src = gx + ((size_t)bc*64 + x0 + xi)*4096;
        for (int i = t; i < 4096; i += 256)
            sx[(i & 63)*65 + (i >> 6)] = src[i];
        __syncthreads();
        float ar0=0, ai0=0, ar1=0, ai1=0;
        #pragma unroll 8
        for (int z = 0; z < 64; z++) {
            float v = sx[z*65 + y];
            float4 e = *(const float4*)&sFZ[z*16 + kzp*4];
            ar0 += v*e.x; ai0 += v*e.y;
            ar1 += v*e.z; ai1 += v*e.w;
        }
        float* pa = &sA[xi*1040 + (kzp*2)*130 + y*2];
        pa[0]   = ar0; pa[1]   = ai0;
        pa[130] = ar1; pa[131] = ai1;
    }
    __syncthreads();
    // stage B: y-reduce
    int xi2 = t >> 6;
    int u   = t & 63;
    int ky0 = (u >> 3) << 1;
    int kz  = u & 7;
    float br0=0, bi0=0, br1=0, bi1=0;
    const float* pa = &sA[xi2*1040 + kz*130];
    #pragma unroll 8
    for (int yy = 0; yy < 64; yy++) {
        float2 a = *(const float2*)&pa[yy*2];
        float4 e = *(const float4*)&sFY[yy*32 + ky0*2];
        br0 += a.x*e.x - a.y*e.y;  bi0 += a.x*e.y + a.y*e.x;
        br1 += a.x*e.z - a.y*e.w;  bi1 += a.x*e.w + a.y*e.z;
    }
    float* dst = T2 + (((size_t)bc*64 + x0 + xi2)*128 + ky0*8 + kz)*2;
    dst[0]  = br0; dst[1]  = bi0;
    dst[16] = br1; dst[17] = bi1;
}

// ---------- F3: x-reduce + Re  T2 -> T3[bc][kx][ky][kz] ----------------------
// grid 1024 = 64 bc * 16 ky, 128 threads
__global__ void k_f3() {
    __shared__ float sT2[64*16];    // [x][kz]c
    __shared__ float sFX[64*32];    // [x][kx]c
    int blk = blockIdx.x;
    int bc = blk >> 4;
    int ky = blk & 15;
    int t = threadIdx.x;
    for (int i = t; i < 2048; i += 128) sFX[i] = d_FX[i];
    for (int i = t; i < 1024; i += 128) {
        int x = i >> 4;
        sT2[i] = T2[(((size_t)bc*64 + x)*128 + ky*8)*2 + (i & 15)];
    }
    __syncthreads();
    int kx = t >> 3;
    int kz = t & 7;
    float acc = 0.f;
    #pragma unroll 8
    for (int x = 0; x < 64; x++) {
        float2 a = *(const float2*)&sT2[x*16 + kz*2];
        float2 e = *(const float2*)&sFX[x*32 + kx*2];
        acc += a.x*e.x - a.y*e.y;
    }
    T3[(size_t)bc*2048 + kx*128 + ky*8 + kz] = acc;
}

// ---------- C: channel mix  T3 -> T4[bco][m]c --------------------------------
// grid 256 = 32 co * 8 chunks, 256 threads; both batches in-block
__global__ void k_c(const float* __restrict__ w1r, const float* __restrict__ w1i,
                    const float* __restrict__ w2r, const float* __restrict__ w2i,
                    const float* __restrict__ w3r, const float* __restrict__ w3i,
                    const float* __restrict__ w4r, const float* __restrict__ w4i) {
    int blk = blockIdx.x;
    int co = blk >> 3;
    int m  = ((blk & 7) << 8) + threadIdx.x;
    int mx = m >> 7, my = (m >> 3) & 15, kz = m & 7;
    int sel = ((my >> 3) << 1) | (mx >> 3);
    const float* wr = (sel==0) ? w1r : (sel==1) ? w2r : (sel==2) ? w3r : w4r;
    const float* wi = (sel==0) ? w1i : (sel==1) ? w2i : (sel==2) ? w3i : w4i;
    int woff = co*512 + (mx & 7)*64 + (my & 7)*8 + kz;
    float aR0=0, aI0=0, aR1=0, aI1=0;
    #pragma unroll 4
    for (int ci = 0; ci < 32; ci++) {
        float x0 = T3[(size_t)ci*2048 + m];
        float x1 = T3[(size_t)(32 + ci)*2048 + m];
        float r  = wr[(size_t)ci*NCO*512 + woff];
        float iw = wi[(size_t)ci*NCO*512 + woff];
        aR0 += x0*r; aI0 += x0*iw;
        aR1 += x1*r; aI1 += x1*iw;
    }
    *(float2*)&T4[((size_t)co*2048 + m)*2]        = make_float2(aR0, aI0);
    *(float2*)&T4[((size_t)(32+co)*2048 + m)*2]   = make_float2(aR1, aI1);
}

// ---------- Ix: x expand  T4 -> T5[bco][x][mm]c ------------------------------
// grid 256 = 64 bco * 4 x-chunks, 256 threads
__global__ void k_ix() {
    __shared__ float sT4[4096];     // [mx][mm]c
    __shared__ float sIX[512];      // [mx][xi]c (16 x per block)
    int blk = blockIdx.x;
    int bco = blk >> 2;
    int xb  = (blk & 3) << 4;
    int t = threadIdx.x;
    for (int i = t; i < 4096; i += 256) sT4[i] = T4[(size_t)bco*4096 + i];
    for (int i = t; i < 512; i += 256) {
        int mx = i >> 5, r = i & 31;
        sIX[i] = d_IX[mx*128 + (xb + (r >> 1))*2 + (r & 1)];
    }
    __syncthreads();
    int mm = t & 127;
    int xh = (t >> 7) << 3;
    float accR[8], accI[8];
    #pragma unroll
    for (int j = 0; j < 8; j++) { accR[j]=0.f; accI[j]=0.f; }
    #pragma unroll
    for (int mx = 0; mx < 16; mx++) {
        float2 a = *(const float2*)&sT4[(mx*128 + mm)*2];
        #pragma unroll
        for (int j = 0; j < 8; j++) {
            float2 e = *(const float2*)&sIX[mx*32 + (xh + j)*2];
            accR[j] += a.x*e.x - a.y*e.y;
            accI[j] += a.x*e.y + a.y*e.x;
        }
    }
    #pragma unroll
    for (int j = 0; j < 8; j++)
        *(float2*)&T5[(((size_t)bco*64 + xb + xh + j)*128 + mm)*2]
            = make_float2(accR[j], accI[j]);
}

// ---------- Iyz: fused y expand + z expand + Re  T5 -> out -------------------
// grid 4096 = 64 bco * 64 x, 256 threads
__global__ void k_iyz(float* __restrict__ out) {
    __shared__ float sU[256];        // [my][kz]c
    __shared__ float sIY[16*130];    // [my][y]c pad
    __shared__ float sA[64*20];      // [y][kz]c pad 20
    __shared__ float sIZ[64*20];     // [z][kz]c pad 20
    int blk = blockIdx.x;
    int bco = blk >> 6;
    int x   = blk & 63;
    int t = threadIdx.x;
    sU[t] = T5[((size_t)bco*64 + x)*256 + t];
    for (int i = t; i < 2048; i += 256)
        sIY[(i >> 7)*130 + (i & 127)] = d_IY[i];
    for (int i = t; i < 1024; i += 256) {
        int kz = i >> 7, zz = (i & 127) >> 1;
        sIZ[zz*20 + kz*2 + (i & 1)] = d_IZ[i];
    }
    __syncthreads();
    // stage A: y expand  [my][kz]c -> sA[y][kz]c
    {
        int kz = t & 7;
        int y  = t >> 3;
        float r0=0,i0=0,r1=0,i1=0;
        #pragma unroll
        for (int my = 0; my < 16; my++) {
            float2 a  = *(const float2*)&sU[my*16 + kz*2];
            float2 e0 = *(const float2*)&sIY[my*130 + y*2];
            float2 e1 = *(const float2*)&sIY[my*130 + (y+32)*2];
            r0 += a.x*e0.x - a.y*e0.y;  i0 += a.x*e0.y + a.y*e0.x;
            r1 += a.x*e1.x - a.y*e1.y;  i1 += a.x*e1.y + a.y*e1.x;
        }
        sA[y*20 + kz*2]        = r0;  sA[y*20 + kz*2 + 1]        = i0;
        sA[(y+32)*20 + kz*2]   = r1;  sA[(y+32)*20 + kz*2 + 1]   = i1;
    }
    __syncthreads();
    // stage B: z expand + Re
    int zh = t & 31;        // z = 2zh, 2zh+1
    int yg = t >> 5;        // y = yg*8 + j
    float4 ez[8];
    #pragma unroll
    for (int zi = 0; zi < 2; zi++)
        #pragma unroll
        for (int kq = 0; kq < 4; kq++)
            ez[zi*4 + kq] = *(const float4*)&sIZ[(zh*2 + zi)*20 + kq*4];
    size_t obase = ((size_t)bco*64 + x)*4096;
    #pragma unroll
    for (int j = 0; j < 8; j++) {
        int y = yg*8 + j;
        float o0 = 0.f, o1 = 0.f;
        #pragma unroll
        for (int kq = 0; kq < 4; kq++) {
            float4 a  = *(const float4*)&sA[y*20 + kq*4];
            float4 e0 = ez[kq];
            float4 e1 = ez[4 + kq];
            o0 += a.x*e0.x - a.y*e0.y + a.z*e0.z - a.w*e0.w;
            o1 += a.x*e1.x - a.y*e1.y + a.z*e1.z - a.w*e1.w;
        }
        *(float2*)&out[obase + y*64 + zh*2] = make_float2(o0, o1);
    }
}

// ---------------- launch -----------------------------------------------------
extern "C" void kernel_launch(void* const* d_in, const int* in_sizes, int n_in,
                              void* d_out, int out_size) {
    const float* x   = (const float*)d_in[0];
    const float* w1r = (const float*)d_in[1];
    const float* w1i = (const float*)d_in[2];
    const float* w2r = (const float*)d_in[3];
    const float* w2i = (const float*)d_in[4];
    const float* w3r = (const float*)d_in[5];
    const float* w3i = (const float*)d_in[6];
    const float* w4r = (const float*)d_in[7];
    const float* w4i = (const float*)d_in[8];
    float* out = (float*)d_out;

    k_init<<<1, 256>>>();
    k_f12<<<1024, 256>>>(x);
    k_f3<<<1024, 128>>>();
    k_c<<<256, 256>>>(w1r, w1i, w2r, w2i, w3r, w3i, w4r, w4i);
    k_ix<<<256, 256>>>();
    k_iyz<<<4096, 256>>>(out);
}

// round 3
// speedup vs baseline: 2.0045x; 1.1792x over previous
#include <cuda_runtime.h>
#include <cuda_bf16.h>
#include <math_constants.h>

#define NB   2
#define NCI  32
#define NCO  32
#define SCALE 3.814697265625e-06f  // 1/64^3

// ---------------- scratch (device globals) -----------------------------------
__device__ float T2[64*64*16*8*2];      // [bc][x][ky][kz]c      4.2 MB
__device__ float T3[64*16*16*8];        // [bc][kx][ky][kz]      0.5 MB
__device__ float T4[64*16*16*8*2];      // [bco][mx][my][kz]c    1.0 MB
__device__ float T5[64*64*16*8*2];      // [bco][x][my][kz]c     4.2 MB

// twiddle tables
__device__ float d_FZ[64*8*2];    // [z][kz]c   e^{-i 2pi kz z/64}
__device__ float d_FY[64*16*2];   // [y][ky]c
__device__ float d_FX[64*16*2];   // [x][kx]c
__device__ float d_IZ[8*64*2];    // [kz][z]c   e^{+i}*SCALE
__device__ float d_IY[16*64*2];   // [my][y]c   e^{+i}
__device__ float d_IX[16*64*2];   // [mx][x]c

__global__ void k_init() {
    int g = blockIdx.x * 256 + threadIdx.x;
    int stride = gridDim.x * 256;
    for (int i = g; i < 64*8; i += stride) {
        int z = i >> 3, kz = i & 7;
        float s, c; sincospif((float)(z*kz) / 32.0f, &s, &c);
        d_FZ[i*2+0] = c; d_FZ[i*2+1] = -s;
    }
    for (int i = g; i < 64*16; i += stride) {
        int n = i >> 4, m = i & 15;
        int k = (m < 8) ? m : (m + 48);
        float s, c; sincospif((float)(n*k) / 32.0f, &s, &c);
        d_FY[i*2] = c; d_FY[i*2+1] = -s;
        d_FX[i*2] = c; d_FX[i*2+1] = -s;
    }
    for (int i = g; i < 8*64; i += stride) {
        int kz = i >> 6, z = i & 63;
        float s, c; sincospif((float)(z*kz) / 32.0f, &s, &c);
        d_IZ[i*2] = c * SCALE; d_IZ[i*2+1] = s * SCALE;
    }
    for (int i = g; i < 16*64; i += stride) {
        int m = i >> 6, n = i & 63;
        int k = (m < 8) ? m : (m + 48);
        float s, c; sincospif((float)(n*k) / 32.0f, &s, &c);
        d_IY[i*2] = c; d_IY[i*2+1] = s;
        d_IX[i*2] = c; d_IX[i*2+1] = s;
    }
}

// ---------- F12: fused z-reduce + y-reduce  x -> T2[bc][x][ky][kz]c ----------
// grid 1024 = 64 bc * 16 x-quads, 256 threads.  Half-period folding on z and y.
__global__ void k_f12(const float* __restrict__ gx) {
    __shared__ float sx[64*65];        // [z][y] transposed, padded
    __shared__ float sA[4*8*130];      // [xi][kz][y]c  row stride 130
    __shared__ float sFZ[64*16];       // [z][kz]c
    __shared__ float sFY[64*32];       // [y][ky]c
    int blk = blockIdx.x;
    int bc = blk >> 4;
    int x0 = (blk & 15) << 2;
    int t = threadIdx.x;
    for (int i = t; i < 1024; i += 256) sFZ[i] = d_FZ[i];
    for (int i = t; i < 2048; i += 256) sFY[i] = d_FY[i];

    int kzp = t & 3;       // kz pair = {2kzp (even), 2kzp+1 (odd)}
    int y   = t >> 2;      // 0..63
    for (int xi = 0; xi < 4; xi++) {
        __syncthreads();
        const float* src = gx + ((size_t)bc*64 + x0 + xi)*4096;
        for (int i = t; i < 4096; i += 256)
            sx[(i & 63)*65 + (i >> 6)] = src[i];
        __syncthreads();
        // fold z and z+32: even kz use v(z)+v(z+32), odd kz use v(z)-v(z+32)
        float arE=0, aiE=0, arO=0, aiO=0;
        #pragma unroll 8
        for (int z = 0; z < 32; z++) {
            float v1 = sx[z*65 + y];
            float v2 = sx[(z+32)*65 + y];
            float vp = v1 + v2, vm = v1 - v2;
            float4 e = *(const float4*)&sFZ[z*16 + kzp*4];
            arE += vp*e.x; aiE += vp*e.y;
            arO += vm*e.z; aiO += vm*e.w;
        }
        float* pa = &sA[xi*1040 + (kzp*2)*130 + y*2];
        pa[0]   = arE; pa[1]   = aiE;
        pa[130] = arO; pa[131] = aiO;
    }
    __syncthreads();
    // stage B: y-reduce with y/y+32 folding
    int xi2 = t >> 6;
    int u   = t & 63;
    int ky0 = (u >> 3) << 1;   // even ky; pair {ky0, ky0+1}
    int kz  = u & 7;
    float br0=0, bi0=0, br1=0, bi1=0;
    const float* pa = &sA[xi2*1040 + kz*130];
    #pragma unroll 8
    for (int yy = 0; yy < 32; yy++) {
        float2 a1 = *(const float2*)&pa[yy*2];
        float2 a2 = *(const float2*)&pa[(yy+32)*2];
        float apR = a1.x + a2.x, apI = a1.y + a2.y;
        float amR = a1.x - a2.x, amI = a1.y - a2.y;
        float4 e = *(const float4*)&sFY[yy*32 + ky0*2];
        br0 += apR*e.x - apI*e.y;  bi0 += apR*e.y + apI*e.x;
        br1 += amR*e.z - amI*e.w;  bi1 += amR*e.w + amI*e.z;
    }
    float* dst = T2 + (((size_t)bc*64 + x0 + xi2)*128 + ky0*8 + kz)*2;
    dst[0]  = br0; dst[1]  = bi0;
    dst[16] = br1; dst[17] = bi1;
}

// ---------- F3: x-reduce + Re  T2 -> T3[bc][kx][ky][kz] ----------------------
// grid 1024 = 64 bc * 16 ky, 128 threads.  x/x+32 folding.
__global__ void k_f3() {
    __shared__ float sT2[64*16];    // [x][kz]c
    __shared__ float sFX[64*32];    // [x][kx]c
    int blk = blockIdx.x;
    int bc = blk >> 4;
    int ky = blk & 15;
    int t = threadIdx.x;
    for (int i = t; i < 2048; i += 128) sFX[i] = d_FX[i];
    for (int i = t; i < 1024; i += 128) {
        int x = i >> 4;
        sT2[i] = T2[(((size_t)bc*64 + x)*128 + ky*8)*2 + (i & 15)];
    }
    __syncthreads();
    int kx = t >> 3;
    int kz = t & 7;
    float sgn = (kx & 1) ? -1.0f : 1.0f;
    float acc = 0.f;
    #pragma unroll 8
    for (int x = 0; x < 32; x++) {
        float2 b1 = *(const float2*)&sT2[x*16 + kz*2];
        float2 b2 = *(const float2*)&sT2[(x+32)*16 + kz*2];
        float bR = fmaf(sgn, b2.x, b1.x);
        float bI = fmaf(sgn, b2.y, b1.y);
        float2 e = *(const float2*)&sFX[x*32 + kx*2];
        acc += bR*e.x - bI*e.y;
    }
    T3[(size_t)bc*2048 + kx*128 + ky*8 + kz] = acc;
}

// ---------- C: channel mix  T3 -> T4[bco][m]c  (float4 vectorized) -----------
// grid 256 = 32 co * 8 chunks, 64 threads; each thread an m-quad, both batches
__global__ void k_c(const float* __restrict__ w1r, const float* __restrict__ w1i,
                    const float* __restrict__ w2r, const float* __restrict__ w2i,
                    const float* __restrict__ w3r, const float* __restrict__ w3i,
                    const float* __restrict__ w4r, const float* __restrict__ w4i) {
    int blk = blockIdx.x;
    int co = blk >> 3;
    int q  = ((blk & 7) << 6) + threadIdx.x;   // 0..511 m-quads
    int m  = q << 2;
    int mx = m >> 7, my = (m >> 3) & 15;
    int sel = ((my >> 3) << 1) | (mx >> 3);
    const float* wr = (sel==0) ? w1r : (sel==1) ? w2r : (sel==2) ? w3r : w4r;
    const float* wi = (sel==0) ? w1i : (sel==1) ? w2i : (sel==2) ? w3i : w4i;
    int woff = co*512 + (mx & 7)*64 + (my & 7)*8 + (m & 7);
    float4 aR0 = {0,0,0,0}, aI0 = {0,0,0,0}, aR1 = {0,0,0,0}, aI1 = {0,0,0,0};
    #pragma unroll 4
    for (int ci = 0; ci < 32; ci++) {
        float4 x0 = *(const float4*)&T3[(size_t)ci*2048 + m];
        float4 x1 = *(const float4*)&T3[(size_t)(32 + ci)*2048 + m];
        float4 r  = __ldg((const float4*)&wr[(size_t)ci*16384 + woff]);
        float4 iw = __ldg((const float4*)&wi[(size_t)ci*16384 + woff]);
        aR0.x += x0.x*r.x;  aR0.y += x0.y*r.y;  aR0.z += x0.z*r.z;  aR0.w += x0.w*r.w;
        aI0.x += x0.x*iw.x; aI0.y += x0.y*iw.y; aI0.z += x0.z*iw.z; aI0.w += x0.w*iw.w;
        aR1.x += x1.x*r.x;  aR1.y += x1.y*r.y;  aR1.z += x1.z*r.z;  aR1.w += x1.w*r.w;
        aI1.x += x1.x*iw.x; aI1.y += x1.y*iw.y; aI1.z += x1.z*iw.z; aI1.w += x1.w*iw.w;
    }
    float* d0 = &T4[((size_t)co*2048 + m)*2];
    *(float4*)d0       = make_float4(aR0.x, aI0.x, aR0.y, aI0.y);
    *(float4*)(d0 + 4) = make_float4(aR0.z, aI0.z, aR0.w, aI0.w);
    float* d1 = &T4[((size_t)(32 + co)*2048 + m)*2];
    *(float4*)d1       = make_float4(aR1.x, aI1.x, aR1.y, aI1.y);
    *(float4*)(d1 + 4) = make_float4(aR1.z, aI1.z, aR1.w, aI1.w);
}

// ---------- Ix: x expand  T4 -> T5[bco][x][mm]c ------------------------------
// grid 256 = 64 bco * 4 x-chunks, 256 threads
__global__ void k_ix() {
    __shared__ float sT4[4096];     // [mx][mm]c
    __shared__ float sIX[512];      // [mx][xi]c (16 x per block)
    int blk = blockIdx.x;
    int bco = blk >> 2;
    int xb  = (blk & 3) << 4;
    int t = threadIdx.x;
    for (int i = t; i < 4096; i += 256) sT4[i] = T4[(size_t)bco*4096 + i];
    for (int i = t; i < 512; i += 256) {
        int mx = i >> 5, r = i & 31;
        sIX[i] = d_IX[mx*128 + (xb + (r >> 1))*2 + (r & 1)];
    }
    __syncthreads();
    int mm = t & 127;
    int xh = (t >> 7) << 3;
    float accR[8], accI[8];
    #pragma unroll
    for (int j = 0; j < 8; j++) { accR[j]=0.f; accI[j]=0.f; }
    #pragma unroll
    for (int mx = 0; mx < 16; mx++) {
        float2 a = *(const float2*)&sT4[(mx*128 + mm)*2];
        #pragma unroll
        for (int j = 0; j < 8; j++) {
            float2 e = *(const float2*)&sIX[mx*32 + (xh + j)*2];
            accR[j] += a.x*e.x - a.y*e.y;
            accI[j] += a.x*e.y + a.y*e.x;
        }
    }
    #pragma unroll
    for (int j = 0; j < 8; j++)
        *(float2*)&T5[(((size_t)bco*64 + xb + xh + j)*128 + mm)*2]
            = make_float2(accR[j], accI[j]);
}

// ---------- Iyz: fused y expand + z expand + Re  T5 -> out -------------------
// grid 4096 = 64 bco * 64 x, 256 threads.  Half-period parity trick on y and z.
__global__ void k_iyz(float* __restrict__ out) {
    __shared__ float sU[256];        // [my][kz]c
    __shared__ float sIY[16*130];    // [my][y]c pad
    __shared__ float sA[64*20];      // [y][kz]c pad 20
    __shared__ float sIZ[64*20];     // [z][kz]c pad 20
    int blk = blockIdx.x;
    int bco = blk >> 6;
    int x   = blk & 63;
    int t = threadIdx.x;
    sU[t] = T5[((size_t)bco*64 + x)*256 + t];
    for (int i = t; i < 2048; i += 256)
        sIY[(i >> 7)*130 + (i & 127)] = d_IY[i];
    for (int i = t; i < 1024; i += 256) {
        int kz = i >> 7, zz = (i & 127) >> 1;
        sIZ[zz*20 + kz*2 + (i & 1)] = d_IZ[i];
    }
    __syncthreads();
    // stage A: y expand; compute y and y+32 together via my-parity accumulators
    {
        int kz = t & 7;
        int yy = t >> 3;   // 0..31
        float reE=0, imE=0, reO=0, imO=0;
        #pragma unroll
        for (int my = 0; my < 16; my++) {
            float2 a = *(const float2*)&sU[my*16 + kz*2];
            float2 e = *(const float2*)&sIY[my*130 + yy*2];
            if ((my & 1) == 0) {
                reE += a.x*e.x - a.y*e.y;  imE += a.x*e.y + a.y*e.x;
            } else {
                reO += a.x*e.x - a.y*e.y;  imO += a.x*e.y + a.y*e.x;
            }
        }
        sA[yy*20 + kz*2]          = reE + reO;
        sA[yy*20 + kz*2 + 1]      = imE + imO;
        sA[(yy+32)*20 + kz*2]     = reE - reO;
        sA[(yy+32)*20 + kz*2 + 1] = imE - imO;
    }
    __syncthreads();
    // stage B: z expand + Re; compute z and z+32 together via kz-parity
    int zz = t & 31;        // z pair (zz, zz+32)
    int yg = t >> 5;        // y = yg*8 + j
    float4 ez[4];
    #pragma unroll
    for (int kq = 0; kq < 4; kq++)
        ez[kq] = *(const float4*)&sIZ[zz*20 + kq*4];
    size_t obase = ((size_t)bco*64 + x)*4096;
    #pragma unroll
    for (int j = 0; j < 8; j++) {
        int y = yg*8 + j;
        float pe = 0.f, po = 0.f;
        #pragma unroll
        for (int kq = 0; kq < 4; kq++) {
            float4 a = *(const float4*)&sA[y*20 + kq*4];
            pe += a.x*ez[kq].x - a.y*ez[kq].y;   // kz = 2kq (even)
            po += a.z*ez[kq].z - a.w*ez[kq].w;   // kz = 2kq+1 (odd)
        }
        out[obase + y*64 + zz]      = pe + po;
        out[obase + y*64 + 32 + zz] = pe - po;
    }
}

// ---------------- launch -----------------------------------------------------
extern "C" void kernel_launch(void* const* d_in, const int* in_sizes, int n_in,
                              void* d_out, int out_size) {
    const float* x   = (const float*)d_in[0];
    const float* w1r = (const float*)d_in[1];
    const float* w1i = (const float*)d_in[2];
    const float* w2r = (const float*)d_in[3];
    const float* w2i = (const float*)d_in[4];
    const float* w3r = (const float*)d_in[5];
    const float* w3i = (const float*)d_in[6];
    const float* w4r = (const float*)d_in[7];
    const float* w4i = (const float*)d_in[8];
    float* out = (float*)d_out;

    k_init<<<16, 256>>>();
    k_f12<<<1024, 256>>>(x);
    k_f3<<<1024, 128>>>();
    k_c<<<256, 64>>>(w1r, w1i, w2r, w2i, w3r, w3i, w4r, w4i);
    k_ix<<<256, 256>>>();
    k_iyz<<<4096, 256>>>(out);
}

// round 4
// speedup vs baseline: 2.3538x; 1.1743x over previous
#include <cuda_runtime.h>
#include <cuda_bf16.h>
#include <math_constants.h>

#define NB   2
#define NCI  32
#define NCO  32
#define SCALE 3.814697265625e-06f  // 1/64^3

// ---------------- scratch (device globals) -----------------------------------
__device__ float T2[64*64*16*8*2];      // [bc][x][ky][kz]c      4.2 MB
__device__ float T3[64*16*16*8];        // [bc][kx][ky][kz]      0.5 MB
__device__ float T4[64*16*16*8*2];      // [bco][mx][my][kz]c    1.0 MB
__device__ float T5[64*64*16*8*2];      // [bco][x][my][kz]c     4.2 MB

// twiddle tables
__device__ float d_FZ[64*8*2];    // [z][kz]c   e^{-i 2pi kz z/64}
__device__ float d_FY[64*16*2];   // [y][ky]c
__device__ float d_FX[64*16*2];   // [x][kx]c
__device__ float d_IZ[8*64*2];    // [kz][z]c   e^{+i}*SCALE
__device__ float d_IY[16*64*2];   // [my][y]c   e^{+i}
__device__ float d_IX[16*64*2];   // [mx][x]c

__global__ void k_init() {
    int g = blockIdx.x * 256 + threadIdx.x;
    int stride = gridDim.x * 256;
    for (int i = g; i < 64*8; i += stride) {
        int z = i >> 3, kz = i & 7;
        float s, c; sincospif((float)(z*kz) / 32.0f, &s, &c);
        d_FZ[i*2+0] = c; d_FZ[i*2+1] = -s;
    }
    for (int i = g; i < 64*16; i += stride) {
        int n = i >> 4, m = i & 15;
        int k = (m < 8) ? m : (m + 48);
        float s, c; sincospif((float)(n*k) / 32.0f, &s, &c);
        d_FY[i*2] = c; d_FY[i*2+1] = -s;
        d_FX[i*2] = c; d_FX[i*2+1] = -s;
    }
    for (int i = g; i < 8*64; i += stride) {
        int kz = i >> 6, z = i & 63;
        float s, c; sincospif((float)(z*kz) / 32.0f, &s, &c);
        d_IZ[i*2] = c * SCALE; d_IZ[i*2+1] = s * SCALE;
    }
    for (int i = g; i < 16*64; i += stride) {
        int m = i >> 6, n = i & 63;
        int k = (m < 8) ? m : (m + 48);
        float s, c; sincospif((float)(n*k) / 32.0f, &s, &c);
        d_IY[i*2] = c; d_IY[i*2+1] = s;
        d_IX[i*2] = c; d_IX[i*2+1] = s;
    }
}

// ---------- F12: fused z-reduce + y-reduce  x -> T2[bc][x][ky][kz]c ----------
// grid 1024 = 64 bc * 16 x-quads, 256 threads.
// Stage A: radix-4 fold on z (classes kz mod 4, one 64-thread group per class).
// Stage B: radix-2 fold on y.
__global__ void k_f12(const float* __restrict__ gx) {
    __shared__ float sx[64*65];        // [z][y] transposed, padded
    __shared__ float sA[4*8*130];      // [xi][kz][y]c  row stride 130
    __shared__ float sFZ[64*16];       // [z][kz]c
    __shared__ float sFY[64*32];       // [y][ky]c
    int blk = blockIdx.x;
    int bc = blk >> 4;
    int x0 = (blk & 15) << 2;
    int t = threadIdx.x;
    for (int i = t; i < 1024; i += 256) sFZ[i] = d_FZ[i];
    for (int i = t; i < 2048; i += 256) sFY[i] = d_FY[i];

    int c = t >> 6;        // kz class: handles kz = c and c+4
    int y = t & 63;
    for (int xi = 0; xi < 4; xi++) {
        __syncthreads();
        const float* src = gx + ((size_t)bc*64 + x0 + xi)*4096;
        for (int i = t; i < 4096; i += 256)
            sx[(i & 63)*65 + (i >> 6)] = src[i];
        __syncthreads();
        float aR0=0, aI0=0, aR1=0, aI1=0;
        #pragma unroll 4
        for (int z = 0; z < 16; z++) {
            float v1 = sx[z*65 + y];
            float v2 = sx[(z+16)*65 + y];
            float v3 = sx[(z+32)*65 + y];
            float v4 = sx[(z+48)*65 + y];
            float2 e0 = *(const float2*)&sFZ[z*16 + c*2];
            float2 e1 = *(const float2*)&sFZ[z*16 + (c+4)*2];
            if ((c & 1) == 0) {
                float f = (c == 0) ? (v1+v3) + (v2+v4) : (v1+v3) - (v2+v4);
                aR0 += f*e0.x; aI0 += f*e0.y;
                aR1 += f*e1.x; aI1 += f*e1.y;
            } else {
                float uR = v1 - v3;
                float uI = (c == 1) ? (v4 - v2) : (v2 - v4);
                aR0 += uR*e0.x - uI*e0.y;  aI0 += uR*e0.y + uI*e0.x;
                aR1 += uR*e1.x - uI*e1.y;  aI1 += uR*e1.y + uI*e1.x;
            }
        }
        float* pa = &sA[xi*1040 + c*130 + y*2];
        pa[0]   = aR0; pa[1]   = aI0;     // kz = c
        pa[520] = aR1; pa[521] = aI1;     // kz = c + 4
    }
    __syncthreads();
    // stage B: y-reduce with y/y+32 folding
    int xi2 = t >> 6;
    int u   = t & 63;
    int ky0 = (u >> 3) << 1;   // even ky; pair {ky0, ky0+1}
    int kz  = u & 7;
    float br0=0, bi0=0, br1=0, bi1=0;
    const float* pa = &sA[xi2*1040 + kz*130];
    #pragma unroll 8
    for (int yy = 0; yy < 32; yy++) {
        float2 a1 = *(const float2*)&pa[yy*2];
        float2 a2 = *(const float2*)&pa[(yy+32)*2];
        float apR = a1.x + a2.x, apI = a1.y + a2.y;
        float amR = a1.x - a2.x, amI = a1.y - a2.y;
        float4 e = *(const float4*)&sFY[yy*32 + ky0*2];
        br0 += apR*e.x - apI*e.y;  bi0 += apR*e.y + apI*e.x;
        br1 += amR*e.z - amI*e.w;  bi1 += amR*e.w + amI*e.z;
    }
    float* dst = T2 + (((size_t)bc*64 + x0 + xi2)*128 + ky0*8 + kz)*2;
    dst[0]  = br0; dst[1]  = bi0;
    dst[16] = br1; dst[17] = bi1;
}

// ---------- F3: x-reduce + Re  T2 -> T3[bc][kx][ky][kz] ----------------------
// grid 1024 = 64 bc * 16 ky, 128 threads.  x/x+32 folding.
__global__ void k_f3() {
    __shared__ float sT2[64*16];    // [x][kz]c
    __shared__ float sFX[64*32];    // [x][kx]c
    int blk = blockIdx.x;
    int bc = blk >> 4;
    int ky = blk & 15;
    int t = threadIdx.x;
    for (int i = t; i < 2048; i += 128) sFX[i] = d_FX[i];
    for (int i = t; i < 1024; i += 128) {
        int x = i >> 4;
        sT2[i] = T2[(((size_t)bc*64 + x)*128 + ky*8)*2 + (i & 15)];
    }
    __syncthreads();
    int kx = t >> 3;
    int kz = t & 7;
    float sgn = (kx & 1) ? -1.0f : 1.0f;
    float acc = 0.f;
    #pragma unroll 8
    for (int x = 0; x < 32; x++) {
        float2 b1 = *(const float2*)&sT2[x*16 + kz*2];
        float2 b2 = *(const float2*)&sT2[(x+32)*16 + kz*2];
        float bR = fmaf(sgn, b2.x, b1.x);
        float bI = fmaf(sgn, b2.y, b1.y);
        float2 e = *(const float2*)&sFX[x*32 + kx*2];
        acc += bR*e.x - bI*e.y;
    }
    T3[(size_t)bc*2048 + kx*128 + ky*8 + kz] = acc;
}

// ---------- C: channel mix  T3 -> T4[bco][m]c --------------------------------
// grid 256 = 32 co * 8 chunks, 256 threads.
// 4 ci-groups of 64 threads; float4 loads; smem cross-group reduction.
__global__ void k_c(const float* __restrict__ w1r, const float* __restrict__ w1i,
                    const float* __restrict__ w2r, const float* __restrict__ w2i,
                    const float* __restrict__ w3r, const float* __restrict__ w3i,
                    const float* __restrict__ w4r, const float* __restrict__ w4i) {
    __shared__ float red[192][17];
    int blk = blockIdx.x;
    int co = blk >> 3;
    int chunk = blk & 7;
    int t = threadIdx.x;
    int g   = t >> 6;          // ci group 0..3
    int q64 = t & 63;          // quad within chunk
    int m = ((chunk << 6) + q64) << 2;
    int mx = m >> 7, my = (m >> 3) & 15;
    int sel = ((my >> 3) << 1) | (mx >> 3);
    const float* wr = (sel==0) ? w1r : (sel==1) ? w2r : (sel==2) ? w3r : w4r;
    const float* wi = (sel==0) ? w1i : (sel==1) ? w2i : (sel==2) ? w3i : w4i;
    int woff = co*512 + (mx & 7)*64 + (my & 7)*8 + (m & 7);
    float acc[16];
    #pragma unroll
    for (int j = 0; j < 16; j++) acc[j] = 0.f;
    int ci0 = g << 3;
    #pragma unroll
    for (int cj = 0; cj < 8; cj++) {
        int ci = ci0 + cj;
        float4 x0 = *(const float4*)&T3[(size_t)ci*2048 + m];
        float4 x1 = *(const float4*)&T3[(size_t)(32 + ci)*2048 + m];
        float4 r  = __ldg((const float4*)&wr[(size_t)ci*16384 + woff]);
        float4 iw = __ldg((const float4*)&wi[(size_t)ci*16384 + woff]);
        acc[0] += x0.x*r.x;  acc[1] += x0.x*iw.x;
        acc[2] += x0.y*r.y;  acc[3] += x0.y*iw.y;
        acc[4] += x0.z*r.z;  acc[5] += x0.z*iw.z;
        acc[6] += x0.w*r.w;  acc[7] += x0.w*iw.w;
        acc[8]  += x1.x*r.x;  acc[9]  += x1.x*iw.x;
        acc[10] += x1.y*r.y;  acc[11] += x1.y*iw.y;
        acc[12] += x1.z*r.z;  acc[13] += x1.z*iw.z;
        acc[14] += x1.w*r.w;  acc[15] += x1.w*iw.w;
    }
    if (g > 0) {
        float* pr = red[(g-1)*64 + q64];
        #pragma unroll
        for (int j = 0; j < 16; j++) pr[j] = acc[j];
    }
    __syncthreads();
    if (g == 0) {
        #pragma unroll
        for (int j = 0; j < 16; j++)
            acc[j] += red[q64][j] + red[64 + q64][j] + red[128 + q64][j];
        float* d0 = &T4[((size_t)co*2048 + m)*2];
        *(float4*)d0       = make_float4(acc[0], acc[1], acc[2], acc[3]);
        *(float4*)(d0 + 4) = make_float4(acc[4], acc[5], acc[6], acc[7]);
        float* d1 = &T4[((size_t)(32 + co)*2048 + m)*2];
        *(float4*)d1       = make_float4(acc[8],  acc[9],  acc[10], acc[11]);
        *(float4*)(d1 + 4) = make_float4(acc[12], acc[13], acc[14], acc[15]);
    }
}

// ---------- Ix: x expand  T4 -> T5[bco][x][mm]c ------------------------------
// grid 256 = 64 bco * 4 x-chunks, 256 threads
__global__ void k_ix() {
    __shared__ float sT4[4096];     // [mx][mm]c
    __shared__ float sIX[512];      // [mx][xi]c (16 x per block)
    int blk = blockIdx.x;
    int bco = blk >> 2;
    int xb  = (blk & 3) << 4;
    int t = threadIdx.x;
    for (int i = t; i < 4096; i += 256) sT4[i] = T4[(size_t)bco*4096 + i];
    for (int i = t; i < 512; i += 256) {
        int mx = i >> 5, r = i & 31;
        sIX[i] = d_IX[mx*128 + (xb + (r >> 1))*2 + (r & 1)];
    }
    __syncthreads();
    int mm = t & 127;
    int xh = (t >> 7) << 3;
    float accR[8], accI[8];
    #pragma unroll
    for (int j = 0; j < 8; j++) { accR[j]=0.f; accI[j]=0.f; }
    #pragma unroll
    for (int mx = 0; mx < 16; mx++) {
        float2 a = *(const float2*)&sT4[(mx*128 + mm)*2];
        #pragma unroll
        for (int j = 0; j < 8; j++) {
            float2 e = *(const float2*)&sIX[mx*32 + (xh + j)*2];
            accR[j] += a.x*e.x - a.y*e.y;
            accI[j] += a.x*e.y + a.y*e.x;
        }
    }
    #pragma unroll
    for (int j = 0; j < 8; j++)
        *(float2*)&T5[(((size_t)bco*64 + xb + xh + j)*128 + mm)*2]
            = make_float2(accR[j], accI[j]);
}

// ---------- Iyz: fused y expand + z expand + Re  T5 -> out -------------------
// grid 4096 = 64 bco * 64 x, 256 threads.  Half-period parity trick on y and z.
__global__ void k_iyz(float* __restrict__ out) {
    __shared__ float sU[256];        // [my][kz]c
    __shared__ float sIY[16*130];    // [my][y]c pad
    __shared__ float sA[64*20];      // [y][kz]c pad 20
    __shared__ float sIZ[64*20];     // [z][kz]c pad 20
    int blk = blockIdx.x;
    int bco = blk >> 6;
    int x   = blk & 63;
    int t = threadIdx.x;
    sU[t] = T5[((size_t)bco*64 + x)*256 + t];
    for (int i = t; i < 2048; i += 256)
        sIY[(i >> 7)*130 + (i & 127)] = d_IY[i];
    for (int i = t; i < 1024; i += 256) {
        int kz = i >> 7, zz = (i & 127) >> 1;
        sIZ[zz*20 + kz*2 + (i & 1)] = d_IZ[i];
    }
    __syncthreads();
    // stage A: y expand; compute y and y+32 together via my-parity accumulators
    {
        int kz = t & 7;
        int yy = t >> 3;   // 0..31
        float reE=0, imE=0, reO=0, imO=0;
        #pragma unroll
        for (int my = 0; my < 16; my++) {
            float2 a = *(const float2*)&sU[my*16 + kz*2];
            float2 e = *(const float2*)&sIY[my*130 + yy*2];
            if ((my & 1) == 0) {
                reE += a.x*e.x - a.y*e.y;  imE += a.x*e.y + a.y*e.x;
            } else {
                reO += a.x*e.x - a.y*e.y;  imO += a.x*e.y + a.y*e.x;
            }
        }
        sA[yy*20 + kz*2]          = reE + reO;
        sA[yy*20 + kz*2 + 1]      = imE + imO;
        sA[(yy+32)*20 + kz*2]     = reE - reO;
        sA[(yy+32)*20 + kz*2 + 1] = imE - imO;
    }
    __syncthreads();
    // stage B: z expand + Re; compute z and z+32 together via kz-parity
    int zz = t & 31;        // z pair (zz, zz+32)
    int yg = t >> 5;        // y = yg*8 + j
    float4 ez[4];
    #pragma unroll
    for (int kq = 0; kq < 4; kq++)
        ez[kq] = *(const float4*)&sIZ[zz*20 + kq*4];
    size_t obase = ((size_t)bco*64 + x)*4096;
    #pragma unroll
    for (int j = 0; j < 8; j++) {
        int y = yg*8 + j;
        float pe = 0.f, po = 0.f;
        #pragma unroll
        for (int kq = 0; kq < 4; kq++) {
            float4 a = *(const float4*)&sA[y*20 + kq*4];
            pe += a.x*ez[kq].x - a.y*ez[kq].y;   // kz = 2kq (even)
            po += a.z*ez[kq].z - a.w*ez[kq].w;   // kz = 2kq+1 (odd)
        }
        out[obase + y*64 + zz]      = pe + po;
        out[obase + y*64 + 32 + zz] = pe - po;
    }
}

// ---------------- launch -----------------------------------------------------
extern "C" void kernel_launch(void* const* d_in, const int* in_sizes, int n_in,
                              void* d_out, int out_size) {
    const float* x   = (const float*)d_in[0];
    const float* w1r = (const float*)d_in[1];
    const float* w1i = (const float*)d_in[2];
    const float* w2r = (const float*)d_in[3];
    const float* w2i = (const float*)d_in[4];
    const float* w3r = (const float*)d_in[5];
    const float* w3i = (const float*)d_in[6];
    const float* w4r = (const float*)d_in[7];
    const float* w4i = (const float*)d_in[8];
    float* out = (float*)d_out;

    k_init<<<16, 256>>>();
    k_f12<<<1024, 256>>>(x);
    k_f3<<<1024, 128>>>();
    k_c<<<256, 256>>>(w1r, w1i, w2r, w2i, w3r, w3i, w4r, w4i);
    k_ix<<<256, 256>>>();
    k_iyz<<<4096, 256>>>(out);
}

// round 5
// speedup vs baseline: 2.5164x; 1.0690x over previous
#include <cuda_runtime.h>
#include <cuda_bf16.h>
#include <math_constants.h>

#define NB   2
#define NCI  32
#define NCO  32
#define SCALE 3.814697265625e-06f  // 1/64^3

// ---------------- scratch (device globals) -----------------------------------
__device__ float T2[64*64*16*8*2];      // [bc][x][ky][kz]c      4.2 MB
__device__ float T3[64*16*16*8];        // [bc][kx][ky][kz]      0.5 MB
__device__ float T4[64*16*16*8*2];      // [bco][mx][my][kz]c    1.0 MB
__device__ float T5[64*64*16*8*2];      // [bco][x][my][kz]c     4.2 MB

__device__ __forceinline__ int kmap(int m) { return (m < 8) ? m : (m + 48); }

// ---------- F12: fused z-reduce + y-reduce  x -> T2[bc][x][ky][kz]c ----------
// grid 1024 = 64 bc * 16 x-quads, 256 threads.
// Stage A: radix-4 fold on z; warp spans 4 kz-classes x 8 y -> 4-way broadcast.
// Stage B: radix-2 fold on y.
__global__ void k_f12(const float* __restrict__ gx) {
    __shared__ float sx[64*65];        // [z][y] transposed, padded
    __shared__ float sA[4*8*130];      // [xi][kz][y]c  row stride 130
    __shared__ float sFZ[64*16];       // [z][kz]c
    __shared__ float sFY[64*32];       // [y][ky]c
    int blk = blockIdx.x;
    int bc = blk >> 4;
    int x0 = (blk & 15) << 2;
    int t = threadIdx.x;
    // twiddles computed in-kernel
    for (int j = t; j < 512; j += 256) {          // sFZ: [z][kz]c
        int z = j >> 3, kz = j & 7;
        float s, c; sincospif((float)(z*kz) / 32.0f, &s, &c);
        sFZ[z*16 + kz*2] = c; sFZ[z*16 + kz*2 + 1] = -s;
    }
    for (int j = t; j < 1024; j += 256) {         // sFY: [y][ky]c
        int y = j >> 4, ky = j & 15;
        float s, c; sincospif((float)(y*kmap(ky)) / 32.0f, &s, &c);
        sFY[y*32 + ky*2] = c; sFY[y*32 + ky*2 + 1] = -s;
    }

    int c = t & 3;         // kz class: handles kz = c and c+4
    int y = t >> 2;        // 0..63
    for (int xi = 0; xi < 4; xi++) {
        __syncthreads();
        const float* src = gx + ((size_t)bc*64 + x0 + xi)*4096;
        for (int i = t; i < 4096; i += 256)
            sx[(i & 63)*65 + (i >> 6)] = src[i];
        __syncthreads();
        float aR0=0, aI0=0, aR1=0, aI1=0;
        #pragma unroll 4
        for (int z = 0; z < 16; z++) {
            float v1 = sx[z*65 + y];
            float v2 = sx[(z+16)*65 + y];
            float v3 = sx[(z+32)*65 + y];
            float v4 = sx[(z+48)*65 + y];
            float2 e0 = *(const float2*)&sFZ[z*16 + c*2];
            float2 e1 = *(const float2*)&sFZ[z*16 + (c+4)*2];
            if ((c & 1) == 0) {
                float f = (c == 0) ? (v1+v3) + (v2+v4) : (v1+v3) - (v2+v4);
                aR0 += f*e0.x; aI0 += f*e0.y;
                aR1 += f*e1.x; aI1 += f*e1.y;
            } else {
                float uR = v1 - v3;
                float uI = (c == 1) ? (v4 - v2) : (v2 - v4);
                aR0 += uR*e0.x - uI*e0.y;  aI0 += uR*e0.y + uI*e0.x;
                aR1 += uR*e1.x - uI*e1.y;  aI1 += uR*e1.y + uI*e1.x;
            }
        }
        float* pa = &sA[xi*1040 + c*130 + y*2];
        pa[0]   = aR0; pa[1]   = aI0;     // kz = c
        pa[520] = aR1; pa[521] = aI1;     // kz = c + 4
    }
    __syncthreads();
    // stage B: y-reduce with y/y+32 folding
    int xi2 = t >> 6;
    int u   = t & 63;
    int ky0 = (u >> 3) << 1;   // even ky; pair {ky0, ky0+1}
    int kz  = u & 7;
    float br0=0, bi0=0, br1=0, bi1=0;
    const float* pa = &sA[xi2*1040 + kz*130];
    #pragma unroll 8
    for (int yy = 0; yy < 32; yy++) {
        float2 a1 = *(const float2*)&pa[yy*2];
        float2 a2 = *(const float2*)&pa[(yy+32)*2];
        float apR = a1.x + a2.x, apI = a1.y + a2.y;
        float amR = a1.x - a2.x, amI = a1.y - a2.y;
        float4 e = *(const float4*)&sFY[yy*32 + ky0*2];
        br0 += apR*e.x - apI*e.y;  bi0 += apR*e.y + apI*e.x;
        br1 += amR*e.z - amI*e.w;  bi1 += amR*e.w + amI*e.z;
    }
    float* dst = T2 + (((size_t)bc*64 + x0 + xi2)*128 + ky0*8 + kz)*2;
    dst[0]  = br0; dst[1]  = bi0;
    dst[16] = br1; dst[17] = bi1;
}

// ---------- F3: x-reduce + Re  T2 -> T3[bc][kx][ky][kz] ----------------------
// grid 1024 = 64 bc * 16 ky, 128 threads.  x/x+32 folding.
__global__ void k_f3() {
    __shared__ float sT2[64*16];    // [x][kz]c
    __shared__ float sFX[64*32];    // [x][kx]c
    int blk = blockIdx.x;
    int bc = blk >> 4;
    int ky = blk & 15;
    int t = threadIdx.x;
    for (int j = t; j < 1024; j += 128) {
        int x = j >> 4, kx = j & 15;
        float s, c; sincospif((float)(x*kmap(kx)) / 32.0f, &s, &c);
        sFX[x*32 + kx*2] = c; sFX[x*32 + kx*2 + 1] = -s;
    }
    for (int i = t; i < 1024; i += 128) {
        int x = i >> 4;
        sT2[i] = T2[(((size_t)bc*64 + x)*128 + ky*8)*2 + (i & 15)];
    }
    __syncthreads();
    int kx = t >> 3;
    int kz = t & 7;
    float sgn = (kx & 1) ? -1.0f : 1.0f;
    float acc = 0.f;
    #pragma unroll 8
    for (int x = 0; x < 32; x++) {
        float2 b1 = *(const float2*)&sT2[x*16 + kz*2];
        float2 b2 = *(const float2*)&sT2[(x+32)*16 + kz*2];
        float bR = fmaf(sgn, b2.x, b1.x);
        float bI = fmaf(sgn, b2.y, b1.y);
        float2 e = *(const float2*)&sFX[x*32 + kx*2];
        acc += bR*e.x - bI*e.y;
    }
    T3[(size_t)bc*2048 + kx*128 + ky*8 + kz] = acc;
}

// ---------- C: channel mix  T3 -> T4[bco][m]c --------------------------------
// grid 512 = 32 co * 16 chunks, 256 threads.
// 8 ci-groups of 32 threads; float4 loads; smem cross-group reduction.
__global__ void k_c(const float* __restrict__ w1r, const float* __restrict__ w1i,
                    const float* __restrict__ w2r, const float* __restrict__ w2i,
                    const float* __restrict__ w3r, const float* __restrict__ w3i,
                    const float* __restrict__ w4r, const float* __restrict__ w4i) {
    __shared__ float red[224][17];
    int blk = blockIdx.x;
    int co = blk >> 4;
    int chunk = blk & 15;
    int t = threadIdx.x;
    int g   = t >> 5;          // ci group 0..7
    int q32 = t & 31;          // quad within chunk
    int m = ((chunk << 5) + q32) << 2;
    int mx = m >> 7, my = (m >> 3) & 15;
    int sel = ((my >> 3) << 1) | (mx >> 3);
    const float* wr = (sel==0) ? w1r : (sel==1) ? w2r : (sel==2) ? w3r : w4r;
    const float* wi = (sel==0) ? w1i : (sel==1) ? w2i : (sel==2) ? w3i : w4i;
    int woff = co*512 + (mx & 7)*64 + (my & 7)*8 + (m & 7);
    float acc[16];
    #pragma unroll
    for (int j = 0; j < 16; j++) acc[j] = 0.f;
    int ci0 = g << 2;
    #pragma unroll
    for (int cj = 0; cj < 4; cj++) {
        int ci = ci0 + cj;
        float4 x0 = *(const float4*)&T3[(size_t)ci*2048 + m];
        float4 x1 = *(const float4*)&T3[(size_t)(32 + ci)*2048 + m];
        float4 r  = __ldg((const float4*)&wr[(size_t)ci*16384 + woff]);
        float4 iw = __ldg((const float4*)&wi[(size_t)ci*16384 + woff]);
        acc[0] += x0.x*r.x;  acc[1] += x0.x*iw.x;
        acc[2] += x0.y*r.y;  acc[3] += x0.y*iw.y;
        acc[4] += x0.z*r.z;  acc[5] += x0.z*iw.z;
        acc[6] += x0.w*r.w;  acc[7] += x0.w*iw.w;
        acc[8]  += x1.x*r.x;  acc[9]  += x1.x*iw.x;
        acc[10] += x1.y*r.y;  acc[11] += x1.y*iw.y;
        acc[12] += x1.z*r.z;  acc[13] += x1.z*iw.z;
        acc[14] += x1.w*r.w;  acc[15] += x1.w*iw.w;
    }
    if (g > 0) {
        float* pr = red[(g-1)*32 + q32];
        #pragma unroll
        for (int j = 0; j < 16; j++) pr[j] = acc[j];
    }
    __syncthreads();
    if (g == 0) {
        #pragma unroll
        for (int k = 0; k < 7; k++) {
            const float* pr = red[k*32 + q32];
            #pragma unroll
            for (int j = 0; j < 16; j++) acc[j] += pr[j];
        }
        float* d0 = &T4[((size_t)co*2048 + m)*2];
        *(float4*)d0       = make_float4(acc[0], acc[1], acc[2], acc[3]);
        *(float4*)(d0 + 4) = make_float4(acc[4], acc[5], acc[6], acc[7]);
        float* d1 = &T4[((size_t)(32 + co)*2048 + m)*2];
        *(float4*)d1       = make_float4(acc[8],  acc[9],  acc[10], acc[11]);
        *(float4*)(d1 + 4) = make_float4(acc[12], acc[13], acc[14], acc[15]);
    }
}

// ---------- Ix: x expand  T4 -> T5[bco][x][mm]c ------------------------------
// grid 256 = 64 bco * 4 x-chunks, 256 threads
__global__ void k_ix() {
    __shared__ float sT4[4096];     // [mx][mm]c
    __shared__ float sIX[512];      // [mx][xi]c (16 x per block)
    int blk = blockIdx.x;
    int bco = blk >> 2;
    int xb  = (blk & 3) << 4;
    int t = threadIdx.x;
    for (int i = t; i < 4096; i += 256) sT4[i] = T4[(size_t)bco*4096 + i];
    {
        int mx = t >> 4, xi = t & 15;
        float s, c; sincospif((float)((xb + xi)*kmap(mx)) / 32.0f, &s, &c);
        sIX[mx*32 + xi*2] = c; sIX[mx*32 + xi*2 + 1] = s;
    }
    __syncthreads();
    int mm = t & 127;
    int xh = (t >> 7) << 3;
    float accR[8], accI[8];
    #pragma unroll
    for (int j = 0; j < 8; j++) { accR[j]=0.f; accI[j]=0.f; }
    #pragma unroll
    for (int mx = 0; mx < 16; mx++) {
        float2 a = *(const float2*)&sT4[(mx*128 + mm)*2];
        #pragma unroll
        for (int j = 0; j < 8; j++) {
            float2 e = *(const float2*)&sIX[mx*32 + (xh + j)*2];
            accR[j] += a.x*e.x - a.y*e.y;
            accI[j] += a.x*e.y + a.y*e.x;
        }
    }
    #pragma unroll
    for (int j = 0; j < 8; j++)
        *(float2*)&T5[(((size_t)bco*64 + xb + xh + j)*128 + mm)*2]
            = make_float2(accR[j], accI[j]);
}

// ---------- Iyz: fused y expand + z expand + Re  T5 -> out -------------------
// grid 4096 = 64 bco * 64 x, 256 threads.  Half-period parity trick on y and z.
__global__ void k_iyz(float* __restrict__ out) {
    __shared__ float sU[256];        // [my][kz]c
    __shared__ float sIY[16*130];    // [my][y]c pad
    __shared__ float sA[64*20];      // [y][kz]c pad 20
    __shared__ float sIZ[64*20];     // [z][kz]c pad 20
    int blk = blockIdx.x;
    int bco = blk >> 6;
    int x   = blk & 63;
    int t = threadIdx.x;
    sU[t] = T5[((size_t)bco*64 + x)*256 + t];
    for (int j = t; j < 1024; j += 256) {       // sIY [my][y]c
        int my = j >> 6, y = j & 63;
        float s, c; sincospif((float)(y*kmap(my)) / 32.0f, &s, &c);
        sIY[my*130 + y*2] = c; sIY[my*130 + y*2 + 1] = s;
    }
    for (int j = t; j < 512; j += 256) {        // sIZ [zz][kz]c (scaled)
        int zz = j >> 3, kz = j & 7;
        float s, c; sincospif((float)(zz*kz) / 32.0f, &s, &c);
        sIZ[zz*20 + kz*2] = c * SCALE; sIZ[zz*20 + kz*2 + 1] = s * SCALE;
    }
    __syncthreads();
    // stage A: y expand; compute y and y+32 together via my-parity accumulators
    {
        int kz = t & 7;
        int yy = t >> 3;   // 0..31
        float reE=0, imE=0, reO=0, imO=0;
        #pragma unroll
        for (int my = 0; my < 16; my++) {
            float2 a = *(const float2*)&sU[my*16 + kz*2];
            float2 e = *(const float2*)&sIY[my*130 + yy*2];
            if ((my & 1) == 0) {
                reE += a.x*e.x - a.y*e.y;  imE += a.x*e.y + a.y*e.x;
            } else {
                reO += a.x*e.x - a.y*e.y;  imO += a.x*e.y + a.y*e.x;
            }
        }
        sA[yy*20 + kz*2]          = reE + reO;
        sA[yy*20 + kz*2 + 1]      = imE + imO;
        sA[(yy+32)*20 + kz*2]     = reE - reO;
        sA[(yy+32)*20 + kz*2 + 1] = imE - imO;
    }
    __syncthreads();
    // stage B: z expand + Re; compute z and z+32 together via kz-parity
    int zz = t & 31;        // z pair (zz, zz+32)
    int yg = t >> 5;        // y = yg*8 + j
    float4 ez[4];
    #pragma unroll
    for (int kq = 0; kq < 4; kq++)
        ez[kq] = *(const float4*)&sIZ[zz*20 + kq*4];
    size_t obase = ((size_t)bco*64 + x)*4096;
    #pragma unroll
    for (int j = 0; j < 8; j++) {
        int y = yg*8 + j;
        float pe = 0.f, po = 0.f;
        #pragma unroll
        for (int kq = 0; kq < 4; kq++) {
            float4 a = *(const float4*)&sA[y*20 + kq*4];
            pe += a.x*ez[kq].x - a.y*ez[kq].y;   // kz = 2kq (even)
            po += a.z*ez[kq].z - a.w*ez[kq].w;   // kz = 2kq+1 (odd)
        }
        out[obase + y*64 + zz]      = pe + po;
        out[obase + y*64 + 32 + zz] = pe - po;
    }
}

// ---------------- launch -----------------------------------------------------
extern "C" void kernel_launch(void* const* d_in, const int* in_sizes, int n_in,
                              void* d_out, int out_size) {
    const float* x   = (const float*)d_in[0];
    const float* w1r = (const float*)d_in[1];
    const float* w1i = (const float*)d_in[2];
    const float* w2r = (const float*)d_in[3];
    const float* w2i = (const float*)d_in[4];
    const float* w3r = (const float*)d_in[5];
    const float* w3i = (const float*)d_in[6];
    const float* w4r = (const float*)d_in[7];
    const float* w4i = (const float*)d_in[8];
    float* out = (float*)d_out;

    k_f12<<<1024, 256>>>(x);
    k_f3<<<1024, 128>>>();
    k_c<<<512, 256>>>(w1r, w1i, w2r, w2i, w3r, w3i, w4r, w4i);
    k_ix<<<256, 256>>>();
    k_iyz<<<4096, 256>>>(out);
}

// round 6
// speedup vs baseline: 2.6717x; 1.0617x over previous
#include <cuda_runtime.h>
#include <cuda_bf16.h>
#include <math_constants.h>

#define NB   2
#define NCI  32
#define NCO  32
#define SCALE 3.814697265625e-06f  // 1/64^3

// ---------------- scratch (device globals) -----------------------------------
__device__ float T2[64*64*16*8*2];      // [bc][x][ky][kz]c      4.2 MB
__device__ float T3[64*16*16*8];        // [bc][kx][ky][kz]      0.5 MB
__device__ float T4[64*16*16*8*2];      // [bco][mx][my][kz]c    1.0 MB

__device__ __forceinline__ int kmap(int m) { return (m < 8) ? m : (m + 48); }

// ---------- F12: fused z-reduce + y-reduce  x -> T2[bc][x][ky][kz]c ----------
// grid 1024 = 64 bc * 16 x-quads, 256 threads.
// Stage A: radix-4 fold on z; warp spans 4 kz-classes x 8 y -> 4-way broadcast.
// Stage B: radix-2 fold on y.
__global__ void k_f12(const float* __restrict__ gx) {
    __shared__ float sx[64*65];        // [z][y] transposed, padded
    __shared__ float sA[4*8*130];      // [xi][kz][y]c  row stride 130
    __shared__ float sFZ[64*16];       // [z][kz]c
    __shared__ float sFY[64*32];       // [y][ky]c
    int blk = blockIdx.x;
    int bc = blk >> 4;
    int x0 = (blk & 15) << 2;
    int t = threadIdx.x;
    // twiddles computed in-kernel
    for (int j = t; j < 512; j += 256) {          // sFZ: [z][kz]c
        int z = j >> 3, kz = j & 7;
        float s, c; sincospif((float)(z*kz) / 32.0f, &s, &c);
        sFZ[z*16 + kz*2] = c; sFZ[z*16 + kz*2 + 1] = -s;
    }
    for (int j = t; j < 1024; j += 256) {         // sFY: [y][ky]c
        int y = j >> 4, ky = j & 15;
        float s, c; sincospif((float)(y*kmap(ky)) / 32.0f, &s, &c);
        sFY[y*32 + ky*2] = c; sFY[y*32 + ky*2 + 1] = -s;
    }

    int c = t & 3;         // kz class: handles kz = c and c+4
    int y = t >> 2;        // 0..63
    for (int xi = 0; xi < 4; xi++) {
        __syncthreads();
        const float* src = gx + ((size_t)bc*64 + x0 + xi)*4096;
        for (int i = t; i < 4096; i += 256)
            sx[(i & 63)*65 + (i >> 6)] = src[i];
        __syncthreads();
        float aR0=0, aI0=0, aR1=0, aI1=0;
        #pragma unroll 4
        for (int z = 0; z < 16; z++) {
            float v1 = sx[z*65 + y];
            float v2 = sx[(z+16)*65 + y];
            float v3 = sx[(z+32)*65 + y];
            float v4 = sx[(z+48)*65 + y];
            float2 e0 = *(const float2*)&sFZ[z*16 + c*2];
            float2 e1 = *(const float2*)&sFZ[z*16 + (c+4)*2];
            if ((c & 1) == 0) {
                float f = (c == 0) ? (v1+v3) + (v2+v4) : (v1+v3) - (v2+v4);
                aR0 += f*e0.x; aI0 += f*e0.y;
                aR1 += f*e1.x; aI1 += f*e1.y;
            } else {
                float uR = v1 - v3;
                float uI = (c == 1) ? (v4 - v2) : (v2 - v4);
                aR0 += uR*e0.x - uI*e0.y;  aI0 += uR*e0.y + uI*e0.x;
                aR1 += uR*e1.x - uI*e1.y;  aI1 += uR*e1.y + uI*e1.x;
            }
        }
        float* pa = &sA[xi*1040 + c*130 + y*2];
        pa[0]   = aR0; pa[1]   = aI0;     // kz = c
        pa[520] = aR1; pa[521] = aI1;     // kz = c + 4
    }
    __syncthreads();
    // stage B: y-reduce with y/y+32 folding
    int xi2 = t >> 6;
    int u   = t & 63;
    int ky0 = (u >> 3) << 1;   // even ky; pair {ky0, ky0+1}
    int kz  = u & 7;
    float br0=0, bi0=0, br1=0, bi1=0;
    const float* pa = &sA[xi2*1040 + kz*130];
    #pragma unroll 8
    for (int yy = 0; yy < 32; yy++) {
        float2 a1 = *(const float2*)&pa[yy*2];
        float2 a2 = *(const float2*)&pa[(yy+32)*2];
        float apR = a1.x + a2.x, apI = a1.y + a2.y;
        float amR = a1.x - a2.x, amI = a1.y - a2.y;
        float4 e = *(const float4*)&sFY[yy*32 + ky0*2];
        br0 += apR*e.x - apI*e.y;  bi0 += apR*e.y + apI*e.x;
        br1 += amR*e.z - amI*e.w;  bi1 += amR*e.w + amI*e.z;
    }
    float* dst = T2 + (((size_t)bc*64 + x0 + xi2)*128 + ky0*8 + kz)*2;
    dst[0]  = br0; dst[1]  = bi0;
    dst[16] = br1; dst[17] = bi1;
}

// ---------- F3: x-reduce + Re  T2 -> T3[bc][kx][ky][kz] ----------------------
// grid 1024 = 64 bc * 16 ky, 128 threads.  x/x+32 folding.
__global__ void k_f3() {
    __shared__ float sT2[64*16];    // [x][kz]c
    __shared__ float sFX[64*32];    // [x][kx]c
    int blk = blockIdx.x;
    int bc = blk >> 4;
    int ky = blk & 15;
    int t = threadIdx.x;
    for (int j = t; j < 1024; j += 128) {
        int x = j >> 4, kx = j & 15;
        float s, c; sincospif((float)(x*kmap(kx)) / 32.0f, &s, &c);
        sFX[x*32 + kx*2] = c; sFX[x*32 + kx*2 + 1] = -s;
    }
    for (int i = t; i < 1024; i += 128) {
        int x = i >> 4;
        sT2[i] = T2[(((size_t)bc*64 + x)*128 + ky*8)*2 + (i & 15)];
    }
    __syncthreads();
    int kx = t >> 3;
    int kz = t & 7;
    float sgn = (kx & 1) ? -1.0f : 1.0f;
    float acc = 0.f;
    #pragma unroll 8
    for (int x = 0; x < 32; x++) {
        float2 b1 = *(const float2*)&sT2[x*16 + kz*2];
        float2 b2 = *(const float2*)&sT2[(x+32)*16 + kz*2];
        float bR = fmaf(sgn, b2.x, b1.x);
        float bI = fmaf(sgn, b2.y, b1.y);
        float2 e = *(const float2*)&sFX[x*32 + kx*2];
        acc += bR*e.x - bI*e.y;
    }
    T3[(size_t)bc*2048 + kx*128 + ky*8 + kz] = acc;
}

// ---------- C: channel mix  T3 -> T4[bco][m]c --------------------------------
// grid 512 = 32 co * 16 chunks, 256 threads.
// 8 ci-groups of 32 threads; float4 loads; smem cross-group reduction.
__global__ void k_c(const float* __restrict__ w1r, const float* __restrict__ w1i,
                    const float* __restrict__ w2r, const float* __restrict__ w2i,
                    const float* __restrict__ w3r, const float* __restrict__ w3i,
                    const float* __restrict__ w4r, const float* __restrict__ w4i) {
    __shared__ float red[224][17];
    int blk = blockIdx.x;
    int co = blk >> 4;
    int chunk = blk & 15;
    int t = threadIdx.x;
    int g   = t >> 5;          // ci group 0..7
    int q32 = t & 31;          // quad within chunk
    int m = ((chunk << 5) + q32) << 2;
    int mx = m >> 7, my = (m >> 3) & 15;
    int sel = ((my >> 3) << 1) | (mx >> 3);
    const float* wr = (sel==0) ? w1r : (sel==1) ? w2r : (sel==2) ? w3r : w4r;
    const float* wi = (sel==0) ? w1i : (sel==1) ? w2i : (sel==2) ? w3i : w4i;
    int woff = co*512 + (mx & 7)*64 + (my & 7)*8 + (m & 7);
    float acc[16];
    #pragma unroll
    for (int j = 0; j < 16; j++) acc[j] = 0.f;
    int ci0 = g << 2;
    #pragma unroll
    for (int cj = 0; cj < 4; cj++) {
        int ci = ci0 + cj;
        float4 x0 = *(const float4*)&T3[(size_t)ci*2048 + m];
        float4 x1 = *(const float4*)&T3[(size_t)(32 + ci)*2048 + m];
        float4 r  = __ldg((const float4*)&wr[(size_t)ci*16384 + woff]);
        float4 iw = __ldg((const float4*)&wi[(size_t)ci*16384 + woff]);
        acc[0] += x0.x*r.x;  acc[1] += x0.x*iw.x;
        acc[2] += x0.y*r.y;  acc[3] += x0.y*iw.y;
        acc[4] += x0.z*r.z;  acc[5] += x0.z*iw.z;
        acc[6] += x0.w*r.w;  acc[7] += x0.w*iw.w;
        acc[8]  += x1.x*r.x;  acc[9]  += x1.x*iw.x;
        acc[10] += x1.y*r.y;  acc[11] += x1.y*iw.y;
        acc[12] += x1.z*r.z;  acc[13] += x1.z*iw.z;
        acc[14] += x1.w*r.w;  acc[15] += x1.w*iw.w;
    }
    if (g > 0) {
        float* pr = red[(g-1)*32 + q32];
        #pragma unroll
        for (int j = 0; j < 16; j++) pr[j] = acc[j];
    }
    __syncthreads();
    if (g == 0) {
        #pragma unroll
        for (int k = 0; k < 7; k++) {
            const float* pr = red[k*32 + q32];
            #pragma unroll
            for (int j = 0; j < 16; j++) acc[j] += pr[j];
        }
        float* d0 = &T4[((size_t)co*2048 + m)*2];
        *(float4*)d0       = make_float4(acc[0], acc[1], acc[2], acc[3]);
        *(float4*)(d0 + 4) = make_float4(acc[4], acc[5], acc[6], acc[7]);
        float* d1 = &T4[((size_t)(32 + co)*2048 + m)*2];
        *(float4*)d1       = make_float4(acc[8],  acc[9],  acc[10], acc[11]);
        *(float4*)(d1 + 4) = make_float4(acc[12], acc[13], acc[14], acc[15]);
    }
}

// ---------- Ixyz: fused x expand + y expand + z expand + Re  T4 -> out -------
// grid 2048 = 64 bco * 32 x-pairs (x, x+32), 256 threads.
// Stage 0: x expand via mx parity; stage A: y expand via my parity;
// stage B: z expand + Re via kz parity.
__global__ void k_ixyz(float* __restrict__ out) {
    __shared__ float sT4[4096];       // [mx][mm]c, mm = my*8+kz
    __shared__ float sU[2][256];      // [xi][my][kz]c
    __shared__ float sEX[32];         // [mx]c for x = xh
    __shared__ float sIY[16*130];     // [my][y]c pad
    __shared__ float sA[2][64*20];    // [xi][y][kz]c pad 20
    __shared__ float sIZ[64*20];      // [zz][kz]c pad 20 (scaled)
    int blk = blockIdx.x;
    int bco = blk >> 5;
    int xh  = blk & 31;               // x = xh, xh+32
    int t = threadIdx.x;
    for (int i = t; i < 4096; i += 256) sT4[i] = T4[(size_t)bco*4096 + i];
    for (int j = t; j < 1024; j += 256) {       // sIY [my][y]c
        int my = j >> 6, y = j & 63;
        float s, c; sincospif((float)(y*kmap(my)) / 32.0f, &s, &c);
        sIY[my*130 + y*2] = c; sIY[my*130 + y*2 + 1] = s;
    }
    for (int j = t; j < 512; j += 256) {        // sIZ [zz][kz]c (scaled)
        int zz = j >> 3, kz = j & 7;
        float s, c; sincospif((float)(zz*kz) / 32.0f, &s, &c);
        sIZ[zz*20 + kz*2] = c * SCALE; sIZ[zz*20 + kz*2 + 1] = s * SCALE;
    }
    if (t < 16) {
        float s, c; sincospif((float)(xh*kmap(t)) / 32.0f, &s, &c);
        sEX[t*2] = c; sEX[t*2+1] = s;
    }
    __syncthreads();
    // stage 0: x expand; x and x+32 together via mx-parity (e(mx,x+32)=(-1)^mx e(mx,x))
    if (t < 128) {
        int mm = t;
        float reE=0, imE=0, reO=0, imO=0;
        #pragma unroll
        for (int mx = 0; mx < 16; mx++) {
            float2 a = *(const float2*)&sT4[(mx*128 + mm)*2];
            float2 e = *(const float2*)&sEX[mx*2];
            float re = a.x*e.x - a.y*e.y;
            float im = a.x*e.y + a.y*e.x;
            if ((mx & 1) == 0) { reE += re; imE += im; }
            else               { reO += re; imO += im; }
        }
        sU[0][mm*2]   = reE + reO;  sU[0][mm*2+1] = imE + imO;
        sU[1][mm*2]   = reE - reO;  sU[1][mm*2+1] = imE - imO;
    }
    __syncthreads();
    // stage A: y expand for both x slices; y and y+32 together via my-parity
    {
        int kz = t & 7;
        int yy = t >> 3;   // 0..31
        #pragma unroll
        for (int xi = 0; xi < 2; xi++) {
            float reE=0, imE=0, reO=0, imO=0;
            #pragma unroll
            for (int my = 0; my < 16; my++) {
                float2 a = *(const float2*)&sU[xi][my*16 + kz*2];
                float2 e = *(const float2*)&sIY[my*130 + yy*2];
                float re = a.x*e.x - a.y*e.y;
                float im = a.x*e.y + a.y*e.x;
                if ((my & 1) == 0) { reE += re; imE += im; }
                else               { reO += re; imO += im; }
            }
            sA[xi][yy*20 + kz*2]          = reE + reO;
            sA[xi][yy*20 + kz*2 + 1]      = imE + imO;
            sA[xi][(yy+32)*20 + kz*2]     = reE - reO;
            sA[xi][(yy+32)*20 + kz*2 + 1] = imE - imO;
        }
    }
    __syncthreads();
    // stage B: z expand + Re for both x slices; z and z+32 via kz-parity
    int zz = t & 31;        // z pair (zz, zz+32)
    int yg = t >> 5;        // y = yg*8 + j
    float4 ez[4];
    #pragma unroll
    for (int kq = 0; kq < 4; kq++)
        ez[kq] = *(const float4*)&sIZ[zz*20 + kq*4];
    #pragma unroll
    for (int xi = 0; xi < 2; xi++) {
        size_t obase = ((size_t)bco*64 + xh + xi*32)*4096;
        #pragma unroll
        for (int j = 0; j < 8; j++) {
            int y = yg*8 + j;
            float pe = 0.f, po = 0.f;
            #pragma unroll
            for (int kq = 0; kq < 4; kq++) {
                float4 a = *(const float4*)&sA[xi][y*20 + kq*4];
                pe += a.x*ez[kq].x - a.y*ez[kq].y;   // kz = 2kq (even)
                po += a.z*ez[kq].z - a.w*ez[kq].w;   // kz = 2kq+1 (odd)
            }
            out[obase + y*64 + zz]      = pe + po;
            out[obase + y*64 + 32 + zz] = pe - po;
        }
    }
}

// ---------------- launch -----------------------------------------------------
extern "C" void kernel_launch(void* const* d_in, const int* in_sizes, int n_in,
                              void* d_out, int out_size) {
    const float* x   = (const float*)d_in[0];
    const float* w1r = (const float*)d_in[1];
    const float* w1i = (const float*)d_in[2];
    const float* w2r = (const float*)d_in[3];
    const float* w2i = (const float*)d_in[4];
    const float* w3r = (const float*)d_in[5];
    const float* w3i = (const float*)d_in[6];
    const float* w4r = (const float*)d_in[7];
    const float* w4i = (const float*)d_in[8];
    float* out = (float*)d_out;

    k_f12<<<1024, 256>>>(x);
    k_f3<<<1024, 128>>>();
    k_c<<<512, 256>>>(w1r, w1i, w2r, w2i, w3r, w3i, w4r, w4i);
    k_ixyz<<<2048, 256>>>(out);
}